// round 1
// baseline (speedup 1.0000x reference)
#include <cuda_runtime.h>

#define N_QUBITS 10
#define TPB 256

// Closed-form evaluation of the 10-qubit staircase circuit:
//   E_0 = cos(x_0 + r_0)
//   E_i = cos(x_i + r_i) * (1 - k_{i-1} * (1 - E_{i-1})),  k_j = sin^2(e_j / 2)
// Derivation: each entangling gate is controlled on qubit i (diagonal in Z_i),
// so <Z_i> is fixed after gate (i-1,i); the 2x2 reduced density matrix recursion
// only propagates its diagonal because the single-qubit states are (c, -i s)
// (one real, one imaginary component) and the controlled rotation is real.
__global__ void qsa_closed_form_kernel(const float* __restrict__ inputs,
                                       const float* __restrict__ rot,
                                       const float* __restrict__ ent,
                                       float* __restrict__ out,
                                       int total_elems) {
    __shared__ float s_buf[TPB * N_QUBITS];
    __shared__ float s_rot[N_QUBITS];
    __shared__ float s_k[N_QUBITS - 1];

    if (threadIdx.x < N_QUBITS) {
        s_rot[threadIdx.x] = rot[threadIdx.x];
    }
    if (threadIdx.x >= 32 && threadIdx.x < 32 + (N_QUBITS - 1)) {
        float sp = sinf(ent[threadIdx.x - 32] * 0.5f);
        s_k[threadIdx.x - 32] = sp * sp;
    }

    const int base = blockIdx.x * (TPB * N_QUBITS);

    // Coalesced staging: whole block loads its 2560 contiguous floats.
    #pragma unroll
    for (int i = threadIdx.x; i < TPB * N_QUBITS; i += TPB) {
        int g = base + i;
        s_buf[i] = (g < total_elems) ? inputs[g] : 0.0f;
    }
    __syncthreads();

    // Each thread handles one sample (10 contiguous floats in smem).
    float* loc = &s_buf[threadIdx.x * N_QUBITS];
    float E[N_QUBITS];
    float carry = 1.0f;  // (1 - k_{i-1} * (1 - E_{i-1})); 1 for i == 0
    #pragma unroll
    for (int i = 0; i < N_QUBITS; i++) {
        float f = cosf(loc[i] + s_rot[i]);
        float e = f * carry;
        E[i] = e;
        if (i < N_QUBITS - 1) {
            carry = 1.0f - s_k[i] * (1.0f - e);
        }
    }

    __syncthreads();  // s_buf reused as output staging
    #pragma unroll
    for (int i = 0; i < N_QUBITS; i++) {
        loc[i] = E[i];
    }
    __syncthreads();

    // Coalesced store.
    #pragma unroll
    for (int i = threadIdx.x; i < TPB * N_QUBITS; i += TPB) {
        int g = base + i;
        if (g < total_elems) out[g] = s_buf[i];
    }
}

extern "C" void kernel_launch(void* const* d_in, const int* in_sizes, int n_in,
                              void* d_out, int out_size) {
    const float* inputs = (const float*)d_in[0];  // (16, 1024, 10) fp32
    const float* rot    = (const float*)d_in[1];  // (10,)
    const float* ent    = (const float*)d_in[2];  // (9,)
    float* out = (float*)d_out;                   // (16, 1024, 10) fp32

    int total_elems = in_sizes[0];                 // 163840
    int T = total_elems / N_QUBITS;                // 16384 samples
    int blocks = (T + TPB - 1) / TPB;              // 64

    qsa_closed_form_kernel<<<blocks, TPB>>>(inputs, rot, ent, out, total_elems);
}

// round 2
// speedup vs baseline: 1.1587x; 1.1587x over previous
#include <cuda_runtime.h>

#define N_QUBITS 10
#define TPB 128
#define F4_PER_BLOCK (TPB * N_QUBITS / 4)   // 320

// Closed-form evaluation of the 10-qubit staircase circuit:
//   E_0 = cos(x_0 + r_0)
//   E_i = cos(x_i + r_i) * (1 - k_{i-1} * (1 - E_{i-1})),  k_j = sin^2(e_j / 2)
// (See R0 derivation: each entangling gate is diagonal in the control qubit's
// Z basis; only the diagonal of the 2x2 reduced density matrix propagates.)
__global__ void qsa_closed_form_kernel(const float4* __restrict__ inputs4,
                                       const float* __restrict__ rot,
                                       const float* __restrict__ ent,
                                       float4* __restrict__ out4,
                                       int total_f4) {
    __shared__ float s_buf[TPB * N_QUBITS];
    __shared__ float s_rot[N_QUBITS];
    __shared__ float s_k[N_QUBITS - 1];

    if (threadIdx.x < N_QUBITS) {
        s_rot[threadIdx.x] = rot[threadIdx.x];
    }
    if (threadIdx.x >= 32 && threadIdx.x < 32 + (N_QUBITS - 1)) {
        float sp = __sinf(ent[threadIdx.x - 32] * 0.5f);
        s_k[threadIdx.x - 32] = sp * sp;
    }

    const int base4 = blockIdx.x * F4_PER_BLOCK;
    float4* s_buf4 = reinterpret_cast<float4*>(s_buf);

    // Coalesced vectorized staging: 320 float4 per block, 2.5 per thread.
    #pragma unroll
    for (int i = threadIdx.x; i < F4_PER_BLOCK; i += TPB) {
        int g = base4 + i;
        if (g < total_f4) s_buf4[i] = inputs4[g];
    }
    __syncthreads();

    // One thread per sample: 10 contiguous floats in smem.
    float* loc = &s_buf[threadIdx.x * N_QUBITS];
    float E[N_QUBITS];
    float carry = 1.0f;
    #pragma unroll
    for (int i = 0; i < N_QUBITS; i++) {
        float f = __cosf(loc[i] + s_rot[i]);   // MUFU path; |arg| small
        float e = f * carry;
        E[i] = e;
        if (i < N_QUBITS - 1) {
            carry = 1.0f - s_k[i] * (1.0f - e);
        }
    }

    __syncthreads();  // reuse s_buf as output staging
    #pragma unroll
    for (int i = 0; i < N_QUBITS; i++) {
        loc[i] = E[i];
    }
    __syncthreads();

    #pragma unroll
    for (int i = threadIdx.x; i < F4_PER_BLOCK; i += TPB) {
        int g = base4 + i;
        if (g < total_f4) out4[g] = s_buf4[i];
    }
}

extern "C" void kernel_launch(void* const* d_in, const int* in_sizes, int n_in,
                              void* d_out, int out_size) {
    const float* inputs = (const float*)d_in[0];  // (16, 1024, 10) fp32
    const float* rot    = (const float*)d_in[1];  // (10,)
    const float* ent    = (const float*)d_in[2];  // (9,)
    float* out = (float*)d_out;

    int total_elems = in_sizes[0];                 // 163840
    int T = total_elems / N_QUBITS;                // 16384 samples
    int blocks = (T + TPB - 1) / TPB;              // 128
    int total_f4 = total_elems / 4;                // 40960

    qsa_closed_form_kernel<<<blocks, TPB>>>(
        reinterpret_cast<const float4*>(inputs), rot, ent,
        reinterpret_cast<float4*>(out), total_f4);
}

// round 3
// speedup vs baseline: 1.1643x; 1.0048x over previous
#include <cuda_runtime.h>

#define N_QUBITS 10
#define TPB 64
#define SPT 2   // samples per thread: 2 samples = 20 floats = 5 aligned float4

// Closed-form evaluation of the 10-qubit staircase circuit:
//   E_0 = cos(x_0 + r_0)
//   E_i = cos(x_i + r_i) * (1 - k_{i-1} * (1 - E_{i-1})),  k_j = sin^2(e_j/2) = (1 - cos e_j)/2
// (R0 derivation: each entangling gate is diagonal in its control qubit's Z
// basis; only the diagonal of the 2x2 reduced density matrix propagates.)
//
// No shared memory, no barriers: each thread owns 2 consecutive samples
// (5 contiguous float4), loads them with full MLP, computes in registers,
// stores 5 float4 back.
__global__ void qsa_closed_form_kernel(const float4* __restrict__ inputs4,
                                       const float* __restrict__ rot,
                                       const float* __restrict__ ent,
                                       float4* __restrict__ out4,
                                       int n_pairs) {
    const int p = blockIdx.x * TPB + threadIdx.x;   // sample-pair index
    if (p >= n_pairs) return;

    // Load 20 floats = 5 float4, all independent (MLP = 5).
    float4 v[5];
    const float4* src = inputs4 + p * 5;
    #pragma unroll
    for (int i = 0; i < 5; i++) v[i] = src[i];

    float x[20];
    #pragma unroll
    for (int i = 0; i < 5; i++) {
        x[4*i+0] = v[i].x; x[4*i+1] = v[i].y; x[4*i+2] = v[i].z; x[4*i+3] = v[i].w;
    }

    // Uniform broadcast loads (one request per warp, L1/L2 cached).
    float r[N_QUBITS], k[N_QUBITS - 1];
    #pragma unroll
    for (int i = 0; i < N_QUBITS; i++) r[i] = __ldg(&rot[i]);
    #pragma unroll
    for (int i = 0; i < N_QUBITS - 1; i++)
        k[i] = 0.5f - 0.5f * __cosf(__ldg(&ent[i]));   // sin^2(e/2)

    float e[20];
    #pragma unroll
    for (int s = 0; s < SPT; s++) {
        float carry = 1.0f;
        #pragma unroll
        for (int i = 0; i < N_QUBITS; i++) {
            float f = __cosf(x[s * N_QUBITS + i] + r[i]);   // MUFU, |arg| small
            float ev = f * carry;
            e[s * N_QUBITS + i] = ev;
            if (i < N_QUBITS - 1) carry = 1.0f - k[i] * (1.0f - ev);
        }
    }

    float4* dst = out4 + p * 5;
    #pragma unroll
    for (int i = 0; i < 5; i++) {
        float4 o;
        o.x = e[4*i+0]; o.y = e[4*i+1]; o.z = e[4*i+2]; o.w = e[4*i+3];
        dst[i] = o;
    }
}

extern "C" void kernel_launch(void* const* d_in, const int* in_sizes, int n_in,
                              void* d_out, int out_size) {
    const float* inputs = (const float*)d_in[0];  // (16, 1024, 10) fp32
    const float* rot    = (const float*)d_in[1];  // (10,)
    const float* ent    = (const float*)d_in[2];  // (9,)
    float* out = (float*)d_out;

    int total_elems = in_sizes[0];                 // 163840
    int T = total_elems / N_QUBITS;                // 16384 samples
    int n_pairs = T / SPT;                         // 8192
    int blocks = (n_pairs + TPB - 1) / TPB;        // 128

    qsa_closed_form_kernel<<<blocks, TPB>>>(
        reinterpret_cast<const float4*>(inputs), rot, ent,
        reinterpret_cast<float4*>(out), n_pairs);
}